// round 3
// baseline (speedup 1.0000x reference)
#include <cuda_runtime.h>
#include <math.h>

#define HDIM 128
#define MAXN 100000
#define MAXE 1600000
#define POOL_SPLIT 8
#define NUM_GRAPHS 100
#define SCAN_BLK 256
#define MAX_BLKS 512
#define GROWS 128          // gemm block row tile
#define WT_PAD 130         // padded k-stride for WsT in smem

// ---------------- scratch (no allocation allowed) ----------------
__device__ float g_Y[MAXN * HDIM];
__device__ float g_hA[MAXN * HDIM];
__device__ float g_hB[MAXN * HDIM];
__device__ float g_WT[3 * HDIM * HDIM];
__device__ float g_ns[MAXN];
__device__ float g_nd[MAXN];
__device__ int   g_odeg[MAXN];
__device__ int   g_ideg[MAXN];
__device__ int   g_off[MAXN];
__device__ int   g_cursor[MAXN];
__device__ int   g_csr_src[MAXE];
__device__ int   g_bsums[MAX_BLKS];

// ---------------- degree counting ----------------
__global__ void zero_deg_kernel(int* odeg, int* ideg, int N) {
    int i = blockIdx.x * blockDim.x + threadIdx.x;
    if (i < N) { odeg[i] = 0; ideg[i] = 0; }
}

__global__ void count_deg_kernel(const int* __restrict__ src,
                                 const int* __restrict__ dst,
                                 int* odeg, int* ideg, int E) {
    int i = blockIdx.x * blockDim.x + threadIdx.x;
    if (i < E) {
        atomicAdd(&odeg[src[i]], 1);
        atomicAdd(&ideg[dst[i]], 1);
    }
}

__global__ void norms_kernel(const int* __restrict__ odeg,
                             const int* __restrict__ ideg,
                             float* ns, float* nd, int N) {
    int i = blockIdx.x * blockDim.x + threadIdx.x;
    if (i < N) {
        ns[i] = rsqrtf((float)(odeg[i] + 1));
        nd[i] = rsqrtf((float)(ideg[i] + 1));
    }
}

// ---------------- prefix sum ----------------
__global__ void blocksum_kernel(const int* __restrict__ deg, int* bsums, int N) {
    __shared__ int s[SCAN_BLK];
    int i = blockIdx.x * SCAN_BLK + threadIdx.x;
    s[threadIdx.x] = (i < N) ? deg[i] : 0;
    __syncthreads();
    for (int o = SCAN_BLK / 2; o > 0; o >>= 1) {
        if (threadIdx.x < o) s[threadIdx.x] += s[threadIdx.x + o];
        __syncthreads();
    }
    if (threadIdx.x == 0) bsums[blockIdx.x] = s[0];
}

__global__ void scan_bsums_kernel(int* bsums, int nblk) {
    __shared__ int s[MAX_BLKS];
    int t = threadIdx.x;
    int v = (t < nblk) ? bsums[t] : 0;
    s[t] = v;
    __syncthreads();
    for (int o = 1; o < MAX_BLKS; o <<= 1) {
        int add = (t >= o) ? s[t - o] : 0;
        __syncthreads();
        s[t] += add;
        __syncthreads();
    }
    if (t < nblk) bsums[t] = s[t] - v;
}

__global__ void write_offsets_kernel(const int* __restrict__ deg,
                                     const int* __restrict__ bsums,
                                     int* off, int* cursor, int N) {
    __shared__ int s[SCAN_BLK];
    int i = blockIdx.x * SCAN_BLK + threadIdx.x;
    int t = threadIdx.x;
    int v = (i < N) ? deg[i] : 0;
    s[t] = v;
    __syncthreads();
    for (int o = 1; o < SCAN_BLK; o <<= 1) {
        int add = (t >= o) ? s[t - o] : 0;
        __syncthreads();
        s[t] += add;
        __syncthreads();
    }
    if (i < N) {
        int ofs = bsums[blockIdx.x] + s[t] - v;
        off[i] = ofs;
        cursor[i] = ofs;
    }
}

__global__ void fill_csr_kernel(const int* __restrict__ src,
                                const int* __restrict__ dst,
                                int* cursor, int* csr_src, int E) {
    int i = blockIdx.x * blockDim.x + threadIdx.x;
    if (i < E) {
        int slot = atomicAdd(&cursor[dst[i]], 1);
        csr_src[slot] = src[i];
    }
}

// ---------------- transpose the 3 weight matrices: WT[c][k] = W[k][c] ----------
__global__ void transposeW_kernel(const float* __restrict__ W1,
                                  const float* __restrict__ W2,
                                  const float* __restrict__ W3,
                                  float* __restrict__ WT) {
    __shared__ float t[32][33];
    int w = blockIdx.x >> 4;          // which weight matrix
    int tile = blockIdx.x & 15;
    int tr = (tile >> 2) * 32;        // k base
    int tc = (tile & 3) * 32;         // c base
    const float* W = (w == 0) ? W1 : ((w == 1) ? W2 : W3);
    int x = threadIdx.x, y0 = threadIdx.y;
    #pragma unroll
    for (int dy = 0; dy < 32; dy += 8)
        t[y0 + dy][x] = W[(tr + y0 + dy) * HDIM + tc + x];
    __syncthreads();
    float* out = WT + w * HDIM * HDIM;
    #pragma unroll
    for (int dy = 0; dy < 32; dy += 8)
        out[(tc + y0 + dy) * HDIM + tr + x] = t[x][y0 + dy];
}

// ---------------- GEMM via fma.rn.f32x2, K-packed ----------------
// Y[row][c] = sum_k (X[row][k]*ns[row]) * W[k][c]
// Block: 256 threads, tile 128 rows x 128 cols.
// warp wid -> rows wid*16..wid*16+15 ; lane l -> cols {l, l+32, l+64, l+96}.
// acc[r][j] packs (even-k partial, odd-k partial); horizontal add at end.
__global__ void __launch_bounds__(256, 1)
gemm_f32x2_kernel(const float* __restrict__ X,
                  const float* __restrict__ ns,
                  const float* __restrict__ WT,   // [c][k], 128x128
                  float* __restrict__ Y, int N) {
    extern __shared__ float smem[];
    float* Xs  = smem;                  // 128 x 128, row-major
    float* WsT = smem + GROWS * HDIM;   // 128 x WT_PAD, c-major

    const int tid  = threadIdx.x;
    const int base = blockIdx.x * GROWS;
    const int lane = tid & 31;
    const int wid  = tid >> 5;

    // load X tile (scaled by ns), coalesced, zero-pad past N
    const float4* X4 = (const float4*)X;
    #pragma unroll
    for (int i = tid; i < GROWS * 32; i += 256) {
        int row = i >> 5, c4 = i & 31;
        int gr = base + row;
        float4 v = make_float4(0.f, 0.f, 0.f, 0.f);
        if (gr < N) {
            v = X4[gr * 32 + c4];
            float s = __ldg(&ns[gr]);
            v.x *= s; v.y *= s; v.z *= s; v.w *= s;
        }
        ((float4*)Xs)[i] = v;
    }
    // load WT coalesced -> WsT padded (conflict-free: lane = k4)
    const float4* WT4 = (const float4*)WT;
    #pragma unroll
    for (int i = tid; i < HDIM * 32; i += 256) {
        int c = i >> 5, k4 = i & 31;
        float4 v = WT4[c * 32 + k4];
        float* p = &WsT[c * WT_PAD + k4 * 4];
        p[0] = v.x; p[1] = v.y; p[2] = v.z; p[3] = v.w;
    }
    __syncthreads();

    unsigned long long acc[16][4];
    #pragma unroll
    for (int r = 0; r < 16; r++)
        #pragma unroll
        for (int j = 0; j < 4; j++) acc[r][j] = 0ULL;

    const float* xrow = Xs + wid * 16 * HDIM;

    #pragma unroll 4
    for (int k = 0; k < HDIM; k += 2) {
        unsigned long long wv[4];
        #pragma unroll
        for (int j = 0; j < 4; j++)
            wv[j] = *(const unsigned long long*)&WsT[(lane + 32 * j) * WT_PAD + k];
        #pragma unroll
        for (int r = 0; r < 16; r++) {
            unsigned long long av = *(const unsigned long long*)&xrow[r * HDIM + k];
            #pragma unroll
            for (int j = 0; j < 4; j++)
                asm volatile("fma.rn.f32x2 %0, %1, %2, %0;"
                             : "+l"(acc[r][j]) : "l"(av), "l"(wv[j]));
        }
    }

    // epilogue: lo + hi, coalesced scalar stores
    #pragma unroll
    for (int r = 0; r < 16; r++) {
        int gr = base + wid * 16 + r;
        if (gr >= N) break;
        #pragma unroll
        for (int j = 0; j < 4; j++) {
            float lo, hi;
            asm("mov.b64 {%0, %1}, %2;" : "=f"(lo), "=f"(hi) : "l"(acc[r][j]));
            Y[gr * HDIM + lane + 32 * j] = lo + hi;
        }
    }
}

// ---------------- fused gather + epilogue ----------------
__global__ void gather_epilogue_kernel(const float* __restrict__ Y,
                                       const int* __restrict__ off,
                                       const int* __restrict__ ideg,
                                       const int* __restrict__ csr_src,
                                       const float* __restrict__ nd,
                                       const float* __restrict__ b,
                                       float* __restrict__ h, int N) {
    int gt = blockIdx.x * blockDim.x + threadIdx.x;
    int n = gt >> 5;
    int lane = threadIdx.x & 31;
    if (n >= N) return;

    const float4* Y4 = (const float4*)Y;
    float4 acc = Y4[n * 32 + lane];   // self-loop
    int o = off[n];
    int d = ideg[n];

    int e = 0;
    for (; e + 4 <= d; e += 4) {
        int s0 = csr_src[o + e + 0];
        int s1 = csr_src[o + e + 1];
        int s2 = csr_src[o + e + 2];
        int s3 = csr_src[o + e + 3];
        float4 v0 = __ldg(&Y4[s0 * 32 + lane]);
        float4 v1 = __ldg(&Y4[s1 * 32 + lane]);
        float4 v2 = __ldg(&Y4[s2 * 32 + lane]);
        float4 v3 = __ldg(&Y4[s3 * 32 + lane]);
        acc.x += v0.x + v1.x + v2.x + v3.x;
        acc.y += v0.y + v1.y + v2.y + v3.y;
        acc.z += v0.z + v1.z + v2.z + v3.z;
        acc.w += v0.w + v1.w + v2.w + v3.w;
    }
    for (; e < d; e++) {
        int s = csr_src[o + e];
        float4 v = __ldg(&Y4[s * 32 + lane]);
        acc.x += v.x; acc.y += v.y; acc.z += v.z; acc.w += v.w;
    }

    float sc = nd[n];
    float4 bb = ((const float4*)b)[lane];
    acc.x = fmaxf(acc.x * sc + bb.x, 0.f);
    acc.y = fmaxf(acc.y * sc + bb.y, 0.f);
    acc.z = fmaxf(acc.z * sc + bb.z, 0.f);
    acc.w = fmaxf(acc.w * sc + bb.w, 0.f);
    ((float4*)h)[n * 32 + lane] = acc;
}

// ---------------- output zero init ----------------
__global__ void zero_out_kernel(float* out, int n) {
    int i = blockIdx.x * blockDim.x + threadIdx.x;
    if (i < n) out[i] = 0.f;
}

// ---------------- pooling ----------------
__global__ void pool_kernel(const float* __restrict__ h,
                            const int* __restrict__ gid,
                            const float* __restrict__ Wp,
                            const float* __restrict__ bp,
                            float* __restrict__ out, int N) {
    const int g    = blockIdx.x / POOL_SPLIT;
    const int part = blockIdx.x % POOL_SPLIT;
    const int tid  = threadIdx.x;

    int lo = 0, hi = N;
    while (lo < hi) { int m = (lo + hi) >> 1; if (gid[m] < g) lo = m + 1; else hi = m; }
    int start = lo;
    lo = start; hi = N;
    while (lo < hi) { int m = (lo + hi) >> 1; if (gid[m] < g + 1) lo = m + 1; else hi = m; }
    int end = lo;

    __shared__ float sWp[HDIM];
    __shared__ float red[4];
    __shared__ float sdot;
    sWp[tid] = Wp[tid];
    float bpv = bp[0];
    __syncthreads();

    float lsum = 0.f;
    float lmax = 0.f;
    const int lane = tid & 31;
    const int warp = tid >> 5;

    for (int n = start + part; n < end; n += POOL_SPLIT) {
        float val = h[n * HDIM + tid];
        float p = val * sWp[tid];
        #pragma unroll
        for (int o = 16; o > 0; o >>= 1)
            p += __shfl_down_sync(0xFFFFFFFFu, p, o);
        if (lane == 0) red[warp] = p;
        __syncthreads();
        if (tid == 0) sdot = red[0] + red[1] + red[2] + red[3] + bpv;
        __syncthreads();
        float w = 1.0f / (1.0f + expf(-sdot));
        lsum += val * w;
        lmax = fmaxf(lmax, val);
        __syncthreads();
    }

    if (end > start) {
        atomicAdd(&out[g * 2 * HDIM + tid], lsum);
        atomicMax((int*)&out[g * 2 * HDIM + HDIM + tid], __float_as_int(lmax));
    }
}

// ---------------- launch ----------------
extern "C" void kernel_launch(void* const* d_in, const int* in_sizes, int n_in,
                              void* d_out, int out_size) {
    const float* node_feats = (const float*)d_in[0];
    const int*   src        = (const int*)d_in[1];
    const int*   dst        = (const int*)d_in[2];
    const int*   gid        = (const int*)d_in[3];
    const float* W1 = (const float*)d_in[4];  const float* b1 = (const float*)d_in[5];
    const float* W2 = (const float*)d_in[6];  const float* b2 = (const float*)d_in[7];
    const float* W3 = (const float*)d_in[8];  const float* b3 = (const float*)d_in[9];
    const float* Wp = (const float*)d_in[10]; const float* bp = (const float*)d_in[11];
    float* out = (float*)d_out;

    const int N = in_sizes[0] / HDIM;
    const int E = in_sizes[1];

    float *pY, *phA, *phB, *pns, *pnd, *pWT;
    int *pod, *pid_, *poff, *pcur, *pcsr, *pbs;
    cudaGetSymbolAddress((void**)&pY,  g_Y);
    cudaGetSymbolAddress((void**)&phA, g_hA);
    cudaGetSymbolAddress((void**)&phB, g_hB);
    cudaGetSymbolAddress((void**)&pWT, g_WT);
    cudaGetSymbolAddress((void**)&pns, g_ns);
    cudaGetSymbolAddress((void**)&pnd, g_nd);
    cudaGetSymbolAddress((void**)&pod, g_odeg);
    cudaGetSymbolAddress((void**)&pid_, g_ideg);
    cudaGetSymbolAddress((void**)&poff, g_off);
    cudaGetSymbolAddress((void**)&pcur, g_cursor);
    cudaGetSymbolAddress((void**)&pcsr, g_csr_src);
    cudaGetSymbolAddress((void**)&pbs, g_bsums);

    const int smem_gemm = (GROWS * HDIM + HDIM * WT_PAD) * (int)sizeof(float); // ~129 KB
    cudaFuncSetAttribute(gemm_f32x2_kernel,
                         cudaFuncAttributeMaxDynamicSharedMemorySize, smem_gemm);

    const int nblk_scan = (N + SCAN_BLK - 1) / SCAN_BLK;

    // --- W transpose (once) + CSR build + norms ---
    transposeW_kernel<<<48, dim3(32, 8)>>>(W1, W2, W3, pWT);
    zero_deg_kernel<<<(N + 255) / 256, 256>>>(pod, pid_, N);
    count_deg_kernel<<<(E + 255) / 256, 256>>>(src, dst, pod, pid_, E);
    norms_kernel<<<(N + 255) / 256, 256>>>(pod, pid_, pns, pnd, N);
    blocksum_kernel<<<nblk_scan, SCAN_BLK>>>(pid_, pbs, N);
    scan_bsums_kernel<<<1, MAX_BLKS>>>(pbs, nblk_scan);
    write_offsets_kernel<<<nblk_scan, SCAN_BLK>>>(pid_, pbs, poff, pcur, N);
    fill_csr_kernel<<<(E + 255) / 256, 256>>>(src, dst, pcur, pcsr, E);

    const int gemm_grid = (N + GROWS - 1) / GROWS;
    const int gather_blocks = (int)(((long long)N * 32 + 255) / 256);

    const float* h_in = node_feats;
    float* h_out_layer[3] = {phA, phB, phA};
    const float* bs[3] = {b1, b2, b3};

    for (int l = 0; l < 3; l++) {
        float* hout = h_out_layer[l];
        gemm_f32x2_kernel<<<gemm_grid, 256, smem_gemm>>>(h_in, pns,
                                                         pWT + l * HDIM * HDIM, pY, N);
        gather_epilogue_kernel<<<gather_blocks, 256>>>(pY, poff, pid_, pcsr,
                                                       pnd, bs[l], hout, N);
        h_in = hout;
    }

    zero_out_kernel<<<(out_size + 255) / 256, 256>>>(out, out_size);
    pool_kernel<<<NUM_GRAPHS * POOL_SPLIT, HDIM>>>(phA, gid, Wp, bp, out, N);
}

// round 4
// speedup vs baseline: 1.0432x; 1.0432x over previous
#include <cuda_runtime.h>
#include <math.h>

#define HDIM 128
#define MAXN 100000
#define MAXE 1600000
#define POOL_SPLIT 8
#define NUM_GRAPHS 100
#define SCAN_BLK 256
#define MAX_BLKS 512

// ---------------- scratch (no allocation allowed) ----------------
__device__ float g_Y[MAXN * HDIM];        // Z = X @ W (unscaled)
__device__ float g_hA[MAXN * HDIM];
__device__ float g_hB[MAXN * HDIM];
__device__ float g_ns[MAXN];
__device__ float g_nd[MAXN];
__device__ int   g_odeg[MAXN];
__device__ int   g_ideg[MAXN];
__device__ int   g_off[MAXN];
__device__ int   g_cursor[MAXN];
__device__ int   g_csr_src[MAXE];
__device__ int   g_bsums[MAX_BLKS];

// ---------------- degree counting ----------------
__global__ void zero_deg_kernel(int* odeg, int* ideg, int N) {
    int i = blockIdx.x * blockDim.x + threadIdx.x;
    if (i < N) { odeg[i] = 0; ideg[i] = 0; }
}

__global__ void count_deg_kernel(const int* __restrict__ src,
                                 const int* __restrict__ dst,
                                 int* odeg, int* ideg, int E) {
    int i = blockIdx.x * blockDim.x + threadIdx.x;
    if (i < E) {
        atomicAdd(&odeg[src[i]], 1);
        atomicAdd(&ideg[dst[i]], 1);
    }
}

__global__ void norms_kernel(const int* __restrict__ odeg,
                             const int* __restrict__ ideg,
                             float* ns, float* nd, int N) {
    int i = blockIdx.x * blockDim.x + threadIdx.x;
    if (i < N) {
        ns[i] = rsqrtf((float)(odeg[i] + 1));   // +1 self-loop
        nd[i] = rsqrtf((float)(ideg[i] + 1));
    }
}

// ---------------- prefix sum ----------------
__global__ void blocksum_kernel(const int* __restrict__ deg, int* bsums, int N) {
    __shared__ int s[SCAN_BLK];
    int i = blockIdx.x * SCAN_BLK + threadIdx.x;
    s[threadIdx.x] = (i < N) ? deg[i] : 0;
    __syncthreads();
    for (int o = SCAN_BLK / 2; o > 0; o >>= 1) {
        if (threadIdx.x < o) s[threadIdx.x] += s[threadIdx.x + o];
        __syncthreads();
    }
    if (threadIdx.x == 0) bsums[blockIdx.x] = s[0];
}

__global__ void scan_bsums_kernel(int* bsums, int nblk) {
    __shared__ int s[MAX_BLKS];
    int t = threadIdx.x;
    int v = (t < nblk) ? bsums[t] : 0;
    s[t] = v;
    __syncthreads();
    for (int o = 1; o < MAX_BLKS; o <<= 1) {
        int add = (t >= o) ? s[t - o] : 0;
        __syncthreads();
        s[t] += add;
        __syncthreads();
    }
    if (t < nblk) bsums[t] = s[t] - v;
}

__global__ void write_offsets_kernel(const int* __restrict__ deg,
                                     const int* __restrict__ bsums,
                                     int* off, int* cursor, int N) {
    __shared__ int s[SCAN_BLK];
    int i = blockIdx.x * SCAN_BLK + threadIdx.x;
    int t = threadIdx.x;
    int v = (i < N) ? deg[i] : 0;
    s[t] = v;
    __syncthreads();
    for (int o = 1; o < SCAN_BLK; o <<= 1) {
        int add = (t >= o) ? s[t - o] : 0;
        __syncthreads();
        s[t] += add;
        __syncthreads();
    }
    if (i < N) {
        int ofs = bsums[blockIdx.x] + s[t] - v;
        off[i] = ofs;
        cursor[i] = ofs;
    }
}

__global__ void fill_csr_kernel(const int* __restrict__ src,
                                const int* __restrict__ dst,
                                int* cursor, int* csr_src, int E) {
    int i = blockIdx.x * blockDim.x + threadIdx.x;
    if (i < E) {
        int slot = atomicAdd(&cursor[dst[i]], 1);
        csr_src[slot] = src[i];
    }
}

// ---------------- GEMM: Z = X @ W (no row scaling; ns applied in gather) ----
__global__ void gemm_kernel(const float* __restrict__ X,
                            const float* __restrict__ W,
                            float* __restrict__ Y, int N) {
    extern __shared__ float smem[];
    float* Ws = smem;                 // 128*128
    float* Xs = smem + HDIM * HDIM;   // 64*128

    const int tid = threadIdx.x;
    const int base = blockIdx.x * 64;

    const float4* W4 = (const float4*)W;
    float4* Ws4 = (float4*)Ws;
    #pragma unroll
    for (int i = tid; i < HDIM * (HDIM / 4); i += 256)
        Ws4[i] = W4[i];

    const float4* X4 = (const float4*)X;
    float4* Xs4 = (float4*)Xs;
    #pragma unroll
    for (int i = tid; i < 64 * (HDIM / 4); i += 256) {
        int row = i >> 5;
        int c4  = i & 31;
        int gr  = base + row;
        float4 v = make_float4(0.f, 0.f, 0.f, 0.f);
        if (gr < N) v = X4[gr * 32 + c4];
        Xs4[i] = v;
    }
    __syncthreads();

    const int rg = tid >> 5;
    const int cg = tid & 31;
    float acc[8][4];
    #pragma unroll
    for (int i = 0; i < 8; i++)
        #pragma unroll
        for (int j = 0; j < 4; j++) acc[i][j] = 0.f;

    const float4* WsV = (const float4*)Ws;
    #pragma unroll 4
    for (int k = 0; k < HDIM; k++) {
        float4 w = WsV[k * 32 + cg];
        #pragma unroll
        for (int i = 0; i < 8; i++) {
            float a = Xs[(rg * 8 + i) * HDIM + k];
            acc[i][0] += a * w.x;
            acc[i][1] += a * w.y;
            acc[i][2] += a * w.z;
            acc[i][3] += a * w.w;
        }
    }

    float4* Y4 = (float4*)Y;
    #pragma unroll
    for (int i = 0; i < 8; i++) {
        int gr = base + rg * 8 + i;
        if (gr < N)
            Y4[gr * 32 + cg] = make_float4(acc[i][0], acc[i][1], acc[i][2], acc[i][3]);
    }
}

// ---------------- fused gather + epilogue (applies ns per-source) ----------
// h[n] = relu(( ns[n]*Z[n] + sum_{s in in(n)} ns[s]*Z[s] ) * nd[n] + b)
__global__ void gather_epilogue_kernel(const float* __restrict__ Z,
                                       const int* __restrict__ off,
                                       const int* __restrict__ ideg,
                                       const int* __restrict__ csr_src,
                                       const float* __restrict__ ns,
                                       const float* __restrict__ nd,
                                       const float* __restrict__ b,
                                       float* __restrict__ h, int N) {
    int gt = blockIdx.x * blockDim.x + threadIdx.x;
    int n = gt >> 5;
    int lane = threadIdx.x & 31;
    if (n >= N) return;

    const float4* Z4 = (const float4*)Z;
    float sn = ns[n];
    float4 self = Z4[n * 32 + lane];
    float4 acc = make_float4(self.x * sn, self.y * sn, self.z * sn, self.w * sn);
    int o = off[n];
    int d = ideg[n];

    int e = 0;
    for (; e + 4 <= d; e += 4) {
        int s0 = csr_src[o + e + 0];
        int s1 = csr_src[o + e + 1];
        int s2 = csr_src[o + e + 2];
        int s3 = csr_src[o + e + 3];
        float n0 = __ldg(&ns[s0]);
        float n1 = __ldg(&ns[s1]);
        float n2 = __ldg(&ns[s2]);
        float n3 = __ldg(&ns[s3]);
        float4 v0 = __ldg(&Z4[s0 * 32 + lane]);
        float4 v1 = __ldg(&Z4[s1 * 32 + lane]);
        float4 v2 = __ldg(&Z4[s2 * 32 + lane]);
        float4 v3 = __ldg(&Z4[s3 * 32 + lane]);
        acc.x += v0.x * n0 + v1.x * n1 + v2.x * n2 + v3.x * n3;
        acc.y += v0.y * n0 + v1.y * n1 + v2.y * n2 + v3.y * n3;
        acc.z += v0.z * n0 + v1.z * n1 + v2.z * n2 + v3.z * n3;
        acc.w += v0.w * n0 + v1.w * n1 + v2.w * n2 + v3.w * n3;
    }
    for (; e < d; e++) {
        int s = csr_src[o + e];
        float nn = __ldg(&ns[s]);
        float4 v = __ldg(&Z4[s * 32 + lane]);
        acc.x += v.x * nn; acc.y += v.y * nn;
        acc.z += v.z * nn; acc.w += v.w * nn;
    }

    float sc = nd[n];
    float4 bb = ((const float4*)b)[lane];
    acc.x = fmaxf(acc.x * sc + bb.x, 0.f);
    acc.y = fmaxf(acc.y * sc + bb.y, 0.f);
    acc.z = fmaxf(acc.z * sc + bb.z, 0.f);
    acc.w = fmaxf(acc.w * sc + bb.w, 0.f);
    ((float4*)h)[n * 32 + lane] = acc;
}

// ---------------- output zero init ----------------
__global__ void zero_out_kernel(float* out, int n) {
    int i = blockIdx.x * blockDim.x + threadIdx.x;
    if (i < n) out[i] = 0.f;
}

// ---------------- pooling ----------------
__global__ void pool_kernel(const float* __restrict__ h,
                            const int* __restrict__ gid,
                            const float* __restrict__ Wp,
                            const float* __restrict__ bp,
                            float* __restrict__ out, int N) {
    const int g    = blockIdx.x / POOL_SPLIT;
    const int part = blockIdx.x % POOL_SPLIT;
    const int tid  = threadIdx.x;

    int lo = 0, hi = N;
    while (lo < hi) { int m = (lo + hi) >> 1; if (gid[m] < g) lo = m + 1; else hi = m; }
    int start = lo;
    lo = start; hi = N;
    while (lo < hi) { int m = (lo + hi) >> 1; if (gid[m] < g + 1) lo = m + 1; else hi = m; }
    int end = lo;

    __shared__ float sWp[HDIM];
    __shared__ float red[4];
    __shared__ float sdot;
    sWp[tid] = Wp[tid];
    float bpv = bp[0];
    __syncthreads();

    float lsum = 0.f;
    float lmax = 0.f;
    const int lane = tid & 31;
    const int warp = tid >> 5;

    for (int n = start + part; n < end; n += POOL_SPLIT) {
        float val = h[n * HDIM + tid];
        float p = val * sWp[tid];
        #pragma unroll
        for (int o = 16; o > 0; o >>= 1)
            p += __shfl_down_sync(0xFFFFFFFFu, p, o);
        if (lane == 0) red[warp] = p;
        __syncthreads();
        if (tid == 0) sdot = red[0] + red[1] + red[2] + red[3] + bpv;
        __syncthreads();
        float w = 1.0f / (1.0f + expf(-sdot));
        lsum += val * w;
        lmax = fmaxf(lmax, val);
        __syncthreads();
    }

    if (end > start) {
        atomicAdd(&out[g * 2 * HDIM + tid], lsum);
        atomicMax((int*)&out[g * 2 * HDIM + HDIM + tid], __float_as_int(lmax));
    }
}

// ---------------- launch ----------------
extern "C" void kernel_launch(void* const* d_in, const int* in_sizes, int n_in,
                              void* d_out, int out_size) {
    const float* node_feats = (const float*)d_in[0];
    const int*   src        = (const int*)d_in[1];
    const int*   dst        = (const int*)d_in[2];
    const int*   gid        = (const int*)d_in[3];
    const float* W1 = (const float*)d_in[4];  const float* b1 = (const float*)d_in[5];
    const float* W2 = (const float*)d_in[6];  const float* b2 = (const float*)d_in[7];
    const float* W3 = (const float*)d_in[8];  const float* b3 = (const float*)d_in[9];
    const float* Wp = (const float*)d_in[10]; const float* bp = (const float*)d_in[11];
    float* out = (float*)d_out;

    const int N = in_sizes[0] / HDIM;
    const int E = in_sizes[1];

    float *pY, *phA, *phB, *pns, *pnd;
    int *pod, *pid_, *poff, *pcur, *pcsr, *pbs;
    cudaGetSymbolAddress((void**)&pY,  g_Y);
    cudaGetSymbolAddress((void**)&phA, g_hA);
    cudaGetSymbolAddress((void**)&phB, g_hB);
    cudaGetSymbolAddress((void**)&pns, g_ns);
    cudaGetSymbolAddress((void**)&pnd, g_nd);
    cudaGetSymbolAddress((void**)&pod, g_odeg);
    cudaGetSymbolAddress((void**)&pid_, g_ideg);
    cudaGetSymbolAddress((void**)&poff, g_off);
    cudaGetSymbolAddress((void**)&pcur, g_cursor);
    cudaGetSymbolAddress((void**)&pcsr, g_csr_src);
    cudaGetSymbolAddress((void**)&pbs, g_bsums);

    const int smem_gemm = (HDIM * HDIM + 64 * HDIM) * (int)sizeof(float);  // 96 KB
    cudaFuncSetAttribute(gemm_kernel,
                         cudaFuncAttributeMaxDynamicSharedMemorySize, smem_gemm);
    cudaFuncSetAttribute(gemm_kernel,
                         cudaFuncAttributePreferredSharedMemoryCarveout, 100);

    const int nblk_scan = (N + SCAN_BLK - 1) / SCAN_BLK;
    const int gemm_grid = (N + 63) / 64;
    const int gather_blocks = (int)(((long long)N * 32 + 255) / 256);

    // --- fork: CSR/norm build on side stream, GEMM1 on main stream ---
    cudaStream_t sB;
    cudaStreamCreateWithFlags(&sB, cudaStreamNonBlocking);
    cudaEvent_t evFork, evJoin;
    cudaEventCreateWithFlags(&evFork, cudaEventDisableTiming);
    cudaEventCreateWithFlags(&evJoin, cudaEventDisableTiming);

    cudaEventRecord(evFork, 0);
    cudaStreamWaitEvent(sB, evFork, 0);

    // side stream: degrees, norms, CSR, output zero-init
    zero_deg_kernel<<<(N + 255) / 256, 256, 0, sB>>>(pod, pid_, N);
    count_deg_kernel<<<(E + 255) / 256, 256, 0, sB>>>(src, dst, pod, pid_, E);
    norms_kernel<<<(N + 255) / 256, 256, 0, sB>>>(pod, pid_, pns, pnd, N);
    blocksum_kernel<<<nblk_scan, SCAN_BLK, 0, sB>>>(pid_, pbs, N);
    scan_bsums_kernel<<<1, MAX_BLKS, 0, sB>>>(pbs, nblk_scan);
    write_offsets_kernel<<<nblk_scan, SCAN_BLK, 0, sB>>>(pid_, pbs, poff, pcur, N);
    fill_csr_kernel<<<(E + 255) / 256, 256, 0, sB>>>(src, dst, pcur, pcsr, E);
    zero_out_kernel<<<(out_size + 255) / 256, 256, 0, sB>>>(out, out_size);

    // main stream: GEMM1 (independent of norms/CSR thanks to ns-commute)
    gemm_kernel<<<gemm_grid, 256, smem_gemm>>>(node_feats, W1, pY, N);

    cudaEventRecord(evJoin, sB);
    cudaStreamWaitEvent(0, evJoin, 0);

    // --- join: layer 1 gather, then layers 2-3 ---
    gather_epilogue_kernel<<<gather_blocks, 256>>>(pY, poff, pid_, pcsr,
                                                   pns, pnd, b1, phA, N);
    gemm_kernel<<<gemm_grid, 256, smem_gemm>>>(phA, W2, pY, N);
    gather_epilogue_kernel<<<gather_blocks, 256>>>(pY, poff, pid_, pcsr,
                                                   pns, pnd, b2, phB, N);
    gemm_kernel<<<gemm_grid, 256, smem_gemm>>>(phB, W3, pY, N);
    gather_epilogue_kernel<<<gather_blocks, 256>>>(pY, poff, pid_, pcsr,
                                                   pns, pnd, b3, phA, N);

    pool_kernel<<<NUM_GRAPHS * POOL_SPLIT, HDIM>>>(phA, gid, Wp, bp, out, N);
    // streams/events intentionally not destroyed (kernel_launch is called only
    // twice outside timing; destruction during capture risks invalidating it)
}

// round 6
// speedup vs baseline: 1.2277x; 1.1768x over previous
#include <cuda_runtime.h>
#include <cuda_bf16.h>
#include <mma.h>
#include <math.h>
#include <stdint.h>

using namespace nvcuda;

#define HDIM 128
#define MAXN 100000
#define MAXE 1600000
#define POOL_SPLIT 8
#define NUM_GRAPHS 100
#define SCAN_BLK 256
#define MAX_BLKS 512

// smem layout for mma gemm (bytes). ldm = 136 bf16 (272B rows, LDSM-friendly)
#define LDA 136
#define SA_HI 0
#define SA_LO (128 * LDA * 2)
#define SB_HI (2 * 128 * LDA * 2)
#define SB_LO (3 * 128 * LDA * 2)
#define SMEM_MMA (4 * 128 * LDA * 2)   // 139264 bytes

// ---------------- scratch (no allocation allowed) ----------------
__device__ float g_Y[MAXN * HDIM];                 // Z (GEMM output, fp32)
__device__ float g_hA[MAXN * HDIM];                // final h (fp32, for pool)
__device__ __nv_bfloat16 g_uhi[MAXN * HDIM];       // GEMM input hi
__device__ __nv_bfloat16 g_ulo[MAXN * HDIM];       // GEMM input lo
__device__ __nv_bfloat16 g_Whi[3 * HDIM * HDIM];   // W hi  [k][n]
__device__ __nv_bfloat16 g_Wlo[3 * HDIM * HDIM];   // W lo  [k][n]
__device__ float g_ns[MAXN];
__device__ float g_nd[MAXN];
__device__ int   g_odeg[MAXN];
__device__ int   g_ideg[MAXN];
__device__ int   g_off[MAXN];
__device__ int   g_cursor[MAXN];
__device__ int   g_csr_src[MAXE];
__device__ int   g_bsums[MAX_BLKS];

// ---------------- degree counting ----------------
__global__ void zero_deg_kernel(int* odeg, int* ideg, int N) {
    int i = blockIdx.x * blockDim.x + threadIdx.x;
    if (i < N) { odeg[i] = 0; ideg[i] = 0; }
}

__global__ void count_deg_kernel(const int* __restrict__ src,
                                 const int* __restrict__ dst,
                                 int* odeg, int* ideg, int E) {
    int i = blockIdx.x * blockDim.x + threadIdx.x;
    if (i < E) {
        atomicAdd(&odeg[src[i]], 1);
        atomicAdd(&ideg[dst[i]], 1);
    }
}

__global__ void norms_kernel(const int* __restrict__ odeg,
                             const int* __restrict__ ideg,
                             float* ns, float* nd, int N) {
    int i = blockIdx.x * blockDim.x + threadIdx.x;
    if (i < N) {
        ns[i] = rsqrtf((float)(odeg[i] + 1));
        nd[i] = rsqrtf((float)(ideg[i] + 1));
    }
}

// ---------------- prefix sum ----------------
__global__ void blocksum_kernel(const int* __restrict__ deg, int* bsums, int N) {
    __shared__ int s[SCAN_BLK];
    int i = blockIdx.x * SCAN_BLK + threadIdx.x;
    s[threadIdx.x] = (i < N) ? deg[i] : 0;
    __syncthreads();
    for (int o = SCAN_BLK / 2; o > 0; o >>= 1) {
        if (threadIdx.x < o) s[threadIdx.x] += s[threadIdx.x + o];
        __syncthreads();
    }
    if (threadIdx.x == 0) bsums[blockIdx.x] = s[0];
}

__global__ void scan_bsums_kernel(int* bsums, int nblk) {
    __shared__ int s[MAX_BLKS];
    int t = threadIdx.x;
    int v = (t < nblk) ? bsums[t] : 0;
    s[t] = v;
    __syncthreads();
    for (int o = 1; o < MAX_BLKS; o <<= 1) {
        int add = (t >= o) ? s[t - o] : 0;
        __syncthreads();
        s[t] += add;
        __syncthreads();
    }
    if (t < nblk) bsums[t] = s[t] - v;
}

__global__ void write_offsets_kernel(const int* __restrict__ deg,
                                     const int* __restrict__ bsums,
                                     int* off, int* cursor, int N) {
    __shared__ int s[SCAN_BLK];
    int i = blockIdx.x * SCAN_BLK + threadIdx.x;
    int t = threadIdx.x;
    int v = (i < N) ? deg[i] : 0;
    s[t] = v;
    __syncthreads();
    for (int o = 1; o < SCAN_BLK; o <<= 1) {
        int add = (t >= o) ? s[t - o] : 0;
        __syncthreads();
        s[t] += add;
        __syncthreads();
    }
    if (i < N) {
        int ofs = bsums[blockIdx.x] + s[t] - v;
        off[i] = ofs;
        cursor[i] = ofs;
    }
}

__global__ void fill_csr_kernel(const int* __restrict__ src,
                                const int* __restrict__ dst,
                                int* cursor, int* csr_src, int E) {
    int i = blockIdx.x * blockDim.x + threadIdx.x;
    if (i < E) {
        int slot = atomicAdd(&cursor[dst[i]], 1);
        csr_src[slot] = src[i];
    }
}

// ---------------- convert W: hi/lo split (no transpose; W is [k][n]) ------
__global__ void convertW_kernel(const float* __restrict__ W1,
                                const float* __restrict__ W2,
                                const float* __restrict__ W3,
                                __nv_bfloat16* __restrict__ Whi,
                                __nv_bfloat16* __restrict__ Wlo) {
    int i = blockIdx.x * blockDim.x + threadIdx.x;
    if (i >= 3 * HDIM * HDIM) return;
    int w = i / (HDIM * HDIM);
    int r = i % (HDIM * HDIM);
    const float* W = (w == 0) ? W1 : ((w == 1) ? W2 : W3);
    float v = W[r];
    __nv_bfloat16 hi = __float2bfloat16(v);
    Whi[i] = hi;
    Wlo[i] = __float2bfloat16(v - __bfloat162float(hi));
}

// ---------------- convert X (fp32 -> bf16 hi/lo), unscaled ----------------
__global__ void convertX_kernel(const float* __restrict__ X,
                                __nv_bfloat16* __restrict__ Xhi,
                                __nv_bfloat16* __restrict__ Xlo, int n4) {
    int i = blockIdx.x * blockDim.x + threadIdx.x;
    if (i >= n4) return;
    float4 v = ((const float4*)X)[i];
    __nv_bfloat16 h0 = __float2bfloat16(v.x);
    __nv_bfloat16 h1 = __float2bfloat16(v.y);
    __nv_bfloat16 h2 = __float2bfloat16(v.z);
    __nv_bfloat16 h3 = __float2bfloat16(v.w);
    __nv_bfloat162* XH = (__nv_bfloat162*)Xhi;
    __nv_bfloat162* XL = (__nv_bfloat162*)Xlo;
    XH[i * 2 + 0] = __halves2bfloat162(h0, h1);
    XH[i * 2 + 1] = __halves2bfloat162(h2, h3);
    XL[i * 2 + 0] = __halves2bfloat162(
        __float2bfloat16(v.x - __bfloat162float(h0)),
        __float2bfloat16(v.y - __bfloat162float(h1)));
    XL[i * 2 + 1] = __halves2bfloat162(
        __float2bfloat16(v.z - __bfloat162float(h2)),
        __float2bfloat16(v.w - __bfloat162float(h3)));
}

// ---------------- wmma split-bf16 GEMM ----------------
// Z[m][n] = sum_k A[m][k]*W[k][n], A=Ahi+Alo, W=Whi+Wlo (drop lo*lo).
// CTA: 128x128 tile, 512 threads = 16 warps (4x4), warp tile 32x32.
__global__ void __launch_bounds__(512)
mma_gemm_kernel(const __nv_bfloat16* __restrict__ Ahi,
                const __nv_bfloat16* __restrict__ Alo,
                const __nv_bfloat16* __restrict__ Whi,
                const __nv_bfloat16* __restrict__ Wlo,
                float* __restrict__ Y, int N) {
    extern __shared__ char smem[];
    __nv_bfloat16* sAhi = (__nv_bfloat16*)(smem + SA_HI);
    __nv_bfloat16* sAlo = (__nv_bfloat16*)(smem + SA_LO);
    __nv_bfloat16* sBhi = (__nv_bfloat16*)(smem + SB_HI);
    __nv_bfloat16* sBlo = (__nv_bfloat16*)(smem + SB_LO);

    const int tid = threadIdx.x;
    const int base = blockIdx.x * 128;
    const bool tail = (base + 128 > N);

    // stage A (hi/lo) and W (hi/lo) into padded smem, uint4 coalesced
    const uint4* AH4 = (const uint4*)Ahi;
    const uint4* AL4 = (const uint4*)Alo;
    const uint4* WH4 = (const uint4*)Whi;
    const uint4* WL4 = (const uint4*)Wlo;
    const uint4 z4 = make_uint4(0, 0, 0, 0);
    #pragma unroll
    for (int i = tid; i < 128 * 16; i += 512) {
        int row = i >> 4, c8 = i & 15;       // 16 uint4 per 128-bf16 row
        int gr = base + row;
        bool ok = gr < N;
        *(uint4*)&sAhi[row * LDA + c8 * 8] = ok ? AH4[gr * 16 + c8] : z4;
        *(uint4*)&sAlo[row * LDA + c8 * 8] = ok ? AL4[gr * 16 + c8] : z4;
        *(uint4*)&sBhi[row * LDA + c8 * 8] = WH4[i];
        *(uint4*)&sBlo[row * LDA + c8 * 8] = WL4[i];
    }
    __syncthreads();

    const int wid = tid >> 5;
    const int wm = wid & 3;     // 0..3 -> rows wm*32
    const int wn = wid >> 2;    // 0..3 -> cols wn*32

    wmma::fragment<wmma::accumulator, 16, 16, 16, float> acc[2][2];
    #pragma unroll
    for (int i = 0; i < 2; i++)
        #pragma unroll
        for (int j = 0; j < 2; j++)
            wmma::fill_fragment(acc[i][j], 0.0f);

    #pragma unroll
    for (int ks = 0; ks < 8; ks++) {
        wmma::fragment<wmma::matrix_a, 16, 16, 16, __nv_bfloat16, wmma::row_major> ahi[2], alo[2];
        wmma::fragment<wmma::matrix_b, 16, 16, 16, __nv_bfloat16, wmma::row_major> bhi[2], blo[2];
        #pragma unroll
        for (int i = 0; i < 2; i++) {
            const __nv_bfloat16* ap = &sAhi[(wm * 32 + i * 16) * LDA + ks * 16];
            const __nv_bfloat16* al = &sAlo[(wm * 32 + i * 16) * LDA + ks * 16];
            wmma::load_matrix_sync(ahi[i], ap, LDA);
            wmma::load_matrix_sync(alo[i], al, LDA);
        }
        #pragma unroll
        for (int j = 0; j < 2; j++) {
            const __nv_bfloat16* bp = &sBhi[(ks * 16) * LDA + wn * 32 + j * 16];
            const __nv_bfloat16* bl = &sBlo[(ks * 16) * LDA + wn * 32 + j * 16];
            wmma::load_matrix_sync(bhi[j], bp, LDA);
            wmma::load_matrix_sync(blo[j], bl, LDA);
        }
        #pragma unroll
        for (int i = 0; i < 2; i++)
            #pragma unroll
            for (int j = 0; j < 2; j++) {
                wmma::mma_sync(acc[i][j], ahi[i], bhi[j], acc[i][j]);
                wmma::mma_sync(acc[i][j], ahi[i], blo[j], acc[i][j]);
                wmma::mma_sync(acc[i][j], alo[i], bhi[j], acc[i][j]);
            }
    }

    if (!tail) {
        #pragma unroll
        for (int i = 0; i < 2; i++)
            #pragma unroll
            for (int j = 0; j < 2; j++)
                wmma::store_matrix_sync(
                    Y + (size_t)(base + wm * 32 + i * 16) * HDIM + wn * 32 + j * 16,
                    acc[i][j], HDIM, wmma::mem_row_major);
    } else {
        // stage through smem with row guard
        __syncthreads();
        float* fs = (float*)smem;   // 128 x 128 fp32 = 64KB < SMEM_MMA
        #pragma unroll
        for (int i = 0; i < 2; i++)
            #pragma unroll
            for (int j = 0; j < 2; j++)
                wmma::store_matrix_sync(
                    fs + (wm * 32 + i * 16) * HDIM + wn * 32 + j * 16,
                    acc[i][j], HDIM, wmma::mem_row_major);
        __syncthreads();
        float4* Y4 = (float4*)Y;
        const float4* fs4 = (const float4*)fs;
        for (int i = tid; i < 128 * 32; i += 512) {
            int row = i >> 5;
            if (base + row < N) Y4[(size_t)(base + row) * 32 + (i & 31)] = fs4[i];
        }
    }
}

// ---------------- fused gather + epilogue + next-layer input prep ----------
// mode 0: per-edge ns (layer 1), out u=ns*h bf16 hi/lo
// mode 1: pre-scaled input, out u bf16 hi/lo
// mode 2: pre-scaled input, out h fp32 (final)
__global__ void gather_kernel(const float* __restrict__ Z,
                              const int* __restrict__ off,
                              const int* __restrict__ ideg,
                              const int* __restrict__ csr_src,
                              const float* __restrict__ ns,
                              const float* __restrict__ nd,
                              const float* __restrict__ b,
                              __nv_bfloat16* __restrict__ uhi,
                              __nv_bfloat16* __restrict__ ulo,
                              float* __restrict__ hout,
                              int mode, int N) {
    int gt = blockIdx.x * blockDim.x + threadIdx.x;
    int n = gt >> 5;
    int lane = threadIdx.x & 31;
    if (n >= N) return;

    const float4* Z4 = (const float4*)Z;
    float4 acc;
    if (mode == 0) {
        float sn = ns[n];
        float4 self = Z4[n * 32 + lane];
        acc = make_float4(self.x * sn, self.y * sn, self.z * sn, self.w * sn);
    } else {
        acc = Z4[n * 32 + lane];
    }
    int o = off[n];
    int d = ideg[n];

    int e = 0;
    if (mode == 0) {
        for (; e + 4 <= d; e += 4) {
            int s0 = csr_src[o + e + 0];
            int s1 = csr_src[o + e + 1];
            int s2 = csr_src[o + e + 2];
            int s3 = csr_src[o + e + 3];
            float n0 = __ldg(&ns[s0]);
            float n1 = __ldg(&ns[s1]);
            float n2 = __ldg(&ns[s2]);
            float n3 = __ldg(&ns[s3]);
            float4 v0 = __ldg(&Z4[s0 * 32 + lane]);
            float4 v1 = __ldg(&Z4[s1 * 32 + lane]);
            float4 v2 = __ldg(&Z4[s2 * 32 + lane]);
            float4 v3 = __ldg(&Z4[s3 * 32 + lane]);
            acc.x += v0.x * n0 + v1.x * n1 + v2.x * n2 + v3.x * n3;
            acc.y += v0.y * n0 + v1.y * n1 + v2.y * n2 + v3.y * n3;
            acc.z += v0.z * n0 + v1.z * n1 + v2.z * n2 + v3.z * n3;
            acc.w += v0.w * n0 + v1.w * n1 + v2.w * n2 + v3.w * n3;
        }
        for (; e < d; e++) {
            int s = csr_src[o + e];
            float nn = __ldg(&ns[s]);
            float4 v = __ldg(&Z4[s * 32 + lane]);
            acc.x += v.x * nn; acc.y += v.y * nn;
            acc.z += v.z * nn; acc.w += v.w * nn;
        }
    } else {
        for (; e + 4 <= d; e += 4) {
            int s0 = csr_src[o + e + 0];
            int s1 = csr_src[o + e + 1];
            int s2 = csr_src[o + e + 2];
            int s3 = csr_src[o + e + 3];
            float4 v0 = __ldg(&Z4[s0 * 32 + lane]);
            float4 v1 = __ldg(&Z4[s1 * 32 + lane]);
            float4 v2 = __ldg(&Z4[s2 * 32 + lane]);
            float4 v3 = __ldg(&Z4[s3 * 32 + lane]);
            acc.x += v0.x + v1.x + v2.x + v3.x;
            acc.y += v0.y + v1.y + v2.y + v3.y;
            acc.z += v0.z + v1.z + v2.z + v3.z;
            acc.w += v0.w + v1.w + v2.w + v3.w;
        }
        for (; e < d; e++) {
            int s = csr_src[o + e];
            float4 v = __ldg(&Z4[s * 32 + lane]);
            acc.x += v.x; acc.y += v.y; acc.z += v.z; acc.w += v.w;
        }
    }

    float sc = nd[n];
    float4 bb = ((const float4*)b)[lane];
    float hx = fmaxf(acc.x * sc + bb.x, 0.f);
    float hy = fmaxf(acc.y * sc + bb.y, 0.f);
    float hz = fmaxf(acc.z * sc + bb.z, 0.f);
    float hw = fmaxf(acc.w * sc + bb.w, 0.f);

    if (mode < 2) {
        float un = ns[n];
        float ux = hx * un, uy = hy * un, uz = hz * un, uw = hw * un;
        __nv_bfloat16 h0 = __float2bfloat16(ux);
        __nv_bfloat16 h1 = __float2bfloat16(uy);
        __nv_bfloat16 h2 = __float2bfloat16(uz);
        __nv_bfloat16 h3 = __float2bfloat16(uw);
        __nv_bfloat162* UH = (__nv_bfloat162*)uhi;
        __nv_bfloat162* UL = (__nv_bfloat162*)ulo;
        int i2 = n * 64 + lane * 2;
        UH[i2 + 0] = __halves2bfloat162(h0, h1);
        UH[i2 + 1] = __halves2bfloat162(h2, h3);
        UL[i2 + 0] = __halves2bfloat162(
            __float2bfloat16(ux - __bfloat162float(h0)),
            __float2bfloat16(uy - __bfloat162float(h1)));
        UL[i2 + 1] = __halves2bfloat162(
            __float2bfloat16(uz - __bfloat162float(h2)),
            __float2bfloat16(uw - __bfloat162float(h3)));
    } else {
        ((float4*)hout)[n * 32 + lane] = make_float4(hx, hy, hz, hw);
    }
}

// ---------------- output zero init ----------------
__global__ void zero_out_kernel(float* out, int n) {
    int i = blockIdx.x * blockDim.x + threadIdx.x;
    if (i < n) out[i] = 0.f;
}

// ---------------- pooling ----------------
__global__ void pool_kernel(const float* __restrict__ h,
                            const int* __restrict__ gid,
                            const float* __restrict__ Wp,
                            const float* __restrict__ bp,
                            float* __restrict__ out, int N) {
    const int g    = blockIdx.x / POOL_SPLIT;
    const int part = blockIdx.x % POOL_SPLIT;
    const int tid  = threadIdx.x;

    int lo = 0, hi = N;
    while (lo < hi) { int m = (lo + hi) >> 1; if (gid[m] < g) lo = m + 1; else hi = m; }
    int start = lo;
    lo = start; hi = N;
    while (lo < hi) { int m = (lo + hi) >> 1; if (gid[m] < g + 1) lo = m + 1; else hi = m; }
    int end = lo;

    __shared__ float sWp[HDIM];
    __shared__ float red[4];
    __shared__ float sdot;
    sWp[tid] = Wp[tid];
    float bpv = bp[0];
    __syncthreads();

    float lsum = 0.f;
    float lmax = 0.f;
    const int lane = tid & 31;
    const int warp = tid >> 5;

    for (int n = start + part; n < end; n += POOL_SPLIT) {
        float val = h[n * HDIM + tid];
        float p = val * sWp[tid];
        #pragma unroll
        for (int o = 16; o > 0; o >>= 1)
            p += __shfl_down_sync(0xFFFFFFFFu, p, o);
        if (lane == 0) red[warp] = p;
        __syncthreads();
        if (tid == 0) sdot = red[0] + red[1] + red[2] + red[3] + bpv;
        __syncthreads();
        float w = 1.0f / (1.0f + expf(-sdot));
        lsum += val * w;
        lmax = fmaxf(lmax, val);
        __syncthreads();
    }

    if (end > start) {
        atomicAdd(&out[g * 2 * HDIM + tid], lsum);
        atomicMax((int*)&out[g * 2 * HDIM + HDIM + tid], __float_as_int(lmax));
    }
}

// ---------------- launch ----------------
extern "C" void kernel_launch(void* const* d_in, const int* in_sizes, int n_in,
                              void* d_out, int out_size) {
    const float* node_feats = (const float*)d_in[0];
    const int*   src        = (const int*)d_in[1];
    const int*   dst        = (const int*)d_in[2];
    const int*   gid        = (const int*)d_in[3];
    const float* W1 = (const float*)d_in[4];  const float* b1 = (const float*)d_in[5];
    const float* W2 = (const float*)d_in[6];  const float* b2 = (const float*)d_in[7];
    const float* W3 = (const float*)d_in[8];  const float* b3 = (const float*)d_in[9];
    const float* Wp = (const float*)d_in[10]; const float* bp = (const float*)d_in[11];
    float* out = (float*)d_out;

    const int N = in_sizes[0] / HDIM;
    const int E = in_sizes[1];

    float *pY, *phA, *pns, *pnd;
    __nv_bfloat16 *puhi, *pulo, *pWhi, *pWlo;
    int *pod, *pid_, *poff, *pcur, *pcsr, *pbs;
    cudaGetSymbolAddress((void**)&pY,   g_Y);
    cudaGetSymbolAddress((void**)&phA,  g_hA);
    cudaGetSymbolAddress((void**)&puhi, g_uhi);
    cudaGetSymbolAddress((void**)&pulo, g_ulo);
    cudaGetSymbolAddress((void**)&pWhi, g_Whi);
    cudaGetSymbolAddress((void**)&pWlo, g_Wlo);
    cudaGetSymbolAddress((void**)&pns, g_ns);
    cudaGetSymbolAddress((void**)&pnd, g_nd);
    cudaGetSymbolAddress((void**)&pod, g_odeg);
    cudaGetSymbolAddress((void**)&pid_, g_ideg);
    cudaGetSymbolAddress((void**)&poff, g_off);
    cudaGetSymbolAddress((void**)&pcur, g_cursor);
    cudaGetSymbolAddress((void**)&pcsr, g_csr_src);
    cudaGetSymbolAddress((void**)&pbs, g_bsums);

    cudaFuncSetAttribute(mma_gemm_kernel,
                         cudaFuncAttributeMaxDynamicSharedMemorySize, SMEM_MMA);

    const int nblk_scan = (N + SCAN_BLK - 1) / SCAN_BLK;
    const int gemm_grid = (N + 127) / 128;
    const int gather_blocks = (int)(((long long)N * 32 + 255) / 256);

    // --- fork: CSR/norm build on side stream; conversions + GEMM1 on main ---
    cudaStream_t sB;
    cudaStreamCreateWithFlags(&sB, cudaStreamNonBlocking);
    cudaEvent_t evFork, evJoin;
    cudaEventCreateWithFlags(&evFork, cudaEventDisableTiming);
    cudaEventCreateWithFlags(&evJoin, cudaEventDisableTiming);

    cudaEventRecord(evFork, 0);
    cudaStreamWaitEvent(sB, evFork, 0);

    zero_deg_kernel<<<(N + 255) / 256, 256, 0, sB>>>(pod, pid_, N);
    count_deg_kernel<<<(E + 255) / 256, 256, 0, sB>>>(src, dst, pod, pid_, E);
    norms_kernel<<<(N + 255) / 256, 256, 0, sB>>>(pod, pid_, pns, pnd, N);
    blocksum_kernel<<<nblk_scan, SCAN_BLK, 0, sB>>>(pid_, pbs, N);
    scan_bsums_kernel<<<1, MAX_BLKS, 0, sB>>>(pbs, nblk_scan);
    write_offsets_kernel<<<nblk_scan, SCAN_BLK, 0, sB>>>(pid_, pbs, poff, pcur, N);
    fill_csr_kernel<<<(E + 255) / 256, 256, 0, sB>>>(src, dst, pcur, pcsr, E);
    zero_out_kernel<<<(out_size + 255) / 256, 256, 0, sB>>>(out, out_size);

    // main: W + X conversion, GEMM1 (independent of norms/CSR)
    convertW_kernel<<<(3 * HDIM * HDIM + 255) / 256, 256>>>(W1, W2, W3, pWhi, pWlo);
    convertX_kernel<<<(N * 32 + 255) / 256, 256>>>(node_feats, puhi, pulo, N * 32);
    mma_gemm_kernel<<<gemm_grid, 512, SMEM_MMA>>>(puhi, pulo, pWhi, pWlo, pY, N);

    cudaEventRecord(evJoin, sB);
    cudaStreamWaitEvent(0, evJoin, 0);

    // --- layer 1 gather (per-edge ns), then layers 2-3 ---
    gather_kernel<<<gather_blocks, 256>>>(pY, poff, pid_, pcsr, pns, pnd, b1,
                                          puhi, pulo, phA, 0, N);
    mma_gemm_kernel<<<gemm_grid, 512, SMEM_MMA>>>(puhi, pulo,
                                                  pWhi + HDIM * HDIM,
                                                  pWlo + HDIM * HDIM, pY, N);
    gather_kernel<<<gather_blocks, 256>>>(pY, poff, pid_, pcsr, pns, pnd, b2,
                                          puhi, pulo, phA, 1, N);
    mma_gemm_kernel<<<gemm_grid, 512, SMEM_MMA>>>(puhi, pulo,
                                                  pWhi + 2 * HDIM * HDIM,
                                                  pWlo + 2 * HDIM * HDIM, pY, N);
    gather_kernel<<<gather_blocks, 256>>>(pY, poff, pid_, pcsr, pns, pnd, b3,
                                          puhi, pulo, phA, 2, N);

    pool_kernel<<<NUM_GRAPHS * POOL_SPLIT, HDIM>>>(phA, gid, Wp, bp, out, N);
    // streams/events intentionally not destroyed (capture safety)
}